// round 3
// baseline (speedup 1.0000x reference)
#include <cuda_runtime.h>
#include <math.h>

// Problem constants
#define Bz   2
#define Lz   2048
#define Ez   1024
#define Hz   16
#define Dz   64
#define BLz  (Bz*Lz)          // 4096 rows
#define E3z  (3*Ez)           // 3072
#define FFz  (4*Ez)           // 4096

// ---------------- static device scratch (no allocations allowed) ----------------
__device__ float g_h  [(long long)BLz*Ez];        // 16 MB  layernorm output
__device__ float g_qkv[(long long)BLz*E3z];       // 48 MB  fused qkv
__device__ float g_S  [(long long)Bz*Hz*Lz*Lz];   // 512 MB attention scores
__device__ float g_att[(long long)BLz*Ez];        // 16 MB  attention output (B,L,E)
__device__ float g_x1 [(long long)BLz*Ez];        // 16 MB  x after attn residual
__device__ float g_ffn[(long long)BLz*FFz];       // 64 MB  gelu(h@W1+b1)

// ---------------- GEMM: 128x128 tile, BK=8, 256 threads, 8x8/thread ----------------
// Assumes M % 128 == 0 and K % 8 == 0 (true for every call here). N is guarded.
enum { EPI_NONE = 0, EPI_BIAS_RES = 1, EPI_BIAS_GELU = 2 };

template<bool TRANSB, int EPI>
__global__ __launch_bounds__(256) void gemm_k(
    const float* __restrict__ A, const float* __restrict__ B, float* __restrict__ C,
    const float* __restrict__ bias, const float* __restrict__ res,
    int M, int N, int K, int lda, int ldb, int ldc,
    int NH,
    long long sAb, long long sAh,
    long long sBb, long long sBh,
    long long sCb, long long sCh)
{
    int z  = blockIdx.z;
    int bb = z / NH, hh = z % NH;
    A += bb * sAb + hh * sAh;
    B += bb * sBb + hh * sBh;
    C += bb * sCb + hh * sCh;
    const float* resp = res;
    if (EPI == EPI_BIAS_RES) resp = res + bb * sCb + hh * sCh;

    __shared__ float As[8][128];
    __shared__ float Bs[8][128];

    int tid = threadIdx.x;
    int tx = tid & 15, ty = tid >> 4;
    int m0 = blockIdx.y * 128, n0 = blockIdx.x * 128;

    float acc[8][8];
    #pragma unroll
    for (int i = 0; i < 8; i++)
        #pragma unroll
        for (int j = 0; j < 8; j++) acc[i][j] = 0.f;

    int arow = tid >> 1, acol = (tid & 1) * 4;     // A-tile: 128 rows x 8 k
    int brow = tid >> 5, bcol = (tid & 31) * 4;    // B-tile NN: 8 k x 128 cols

    for (int k0 = 0; k0 < K; k0 += 8) {
        float4 av = *reinterpret_cast<const float4*>(
            &A[(long long)(m0 + arow) * lda + k0 + acol]);
        As[acol + 0][arow] = av.x; As[acol + 1][arow] = av.y;
        As[acol + 2][arow] = av.z; As[acol + 3][arow] = av.w;

        if (!TRANSB) {
            float4 bv = make_float4(0.f, 0.f, 0.f, 0.f);
            if (n0 + bcol < N)
                bv = *reinterpret_cast<const float4*>(
                    &B[(long long)(k0 + brow) * ldb + n0 + bcol]);
            *reinterpret_cast<float4*>(&Bs[brow][bcol]) = bv;
        } else {
            float4 bv = make_float4(0.f, 0.f, 0.f, 0.f);
            if (n0 + arow < N)
                bv = *reinterpret_cast<const float4*>(
                    &B[(long long)(n0 + arow) * ldb + k0 + acol]);
            Bs[acol + 0][arow] = bv.x; Bs[acol + 1][arow] = bv.y;
            Bs[acol + 2][arow] = bv.z; Bs[acol + 3][arow] = bv.w;
        }
        __syncthreads();

        #pragma unroll
        for (int kk = 0; kk < 8; kk++) {
            float a[8], b[8];
            *reinterpret_cast<float4*>(&a[0]) = *reinterpret_cast<const float4*>(&As[kk][ty * 4]);
            *reinterpret_cast<float4*>(&a[4]) = *reinterpret_cast<const float4*>(&As[kk][64 + ty * 4]);
            *reinterpret_cast<float4*>(&b[0]) = *reinterpret_cast<const float4*>(&Bs[kk][tx * 4]);
            *reinterpret_cast<float4*>(&b[4]) = *reinterpret_cast<const float4*>(&Bs[kk][64 + tx * 4]);
            #pragma unroll
            for (int i = 0; i < 8; i++)
                #pragma unroll
                for (int j = 0; j < 8; j++)
                    acc[i][j] += a[i] * b[j];
        }
        __syncthreads();
    }

    #pragma unroll
    for (int i = 0; i < 8; i++) {
        int r = m0 + ((i < 4) ? (ty * 4 + i) : (64 + ty * 4 + i - 4));
        #pragma unroll
        for (int j = 0; j < 8; j++) {
            int c = n0 + ((j < 4) ? (tx * 4 + j) : (64 + tx * 4 + j - 4));
            if (c < N) {
                float v = acc[i][j];
                if (EPI == EPI_BIAS_RES)
                    v += bias[c] + resp[(long long)r * ldc + c];
                if (EPI == EPI_BIAS_GELU) {
                    v += bias[c];
                    v = 0.5f * v * (1.f + erff(v * 0.70710678118654752f));
                }
                C[(long long)r * ldc + c] = v;
            }
        }
    }
}

// ---------------- LayerNorm: one block per row of E=1024 ----------------
__global__ __launch_bounds__(256) void ln_k(
    const float* __restrict__ x, const float* __restrict__ g,
    const float* __restrict__ b, float* __restrict__ y)
{
    __shared__ float sh_s[8];
    __shared__ float sh_q[8];
    long long row = blockIdx.x;
    const float* xr = x + row * Ez;
    int t = threadIdx.x;

    float4 v = reinterpret_cast<const float4*>(xr)[t];
    float s  = v.x + v.y + v.z + v.w;
    float sq = v.x * v.x + v.y * v.y + v.z * v.z + v.w * v.w;
    #pragma unroll
    for (int o = 16; o > 0; o >>= 1) {
        s  += __shfl_down_sync(0xffffffffu, s,  o);
        sq += __shfl_down_sync(0xffffffffu, sq, o);
    }
    int warp = t >> 5, lane = t & 31;
    if (lane == 0) { sh_s[warp] = s; sh_q[warp] = sq; }
    __syncthreads();
    if (warp == 0) {
        s  = (lane < 8) ? sh_s[lane] : 0.f;
        sq = (lane < 8) ? sh_q[lane] : 0.f;
        #pragma unroll
        for (int o = 4; o > 0; o >>= 1) {
            s  += __shfl_down_sync(0xffffffffu, s,  o);
            sq += __shfl_down_sync(0xffffffffu, sq, o);
        }
        if (lane == 0) { sh_s[0] = s; sh_q[0] = sq; }
    }
    __syncthreads();
    float mu  = sh_s[0] * (1.f / Ez);
    float var = sh_q[0] * (1.f / Ez) - mu * mu;
    float inv = rsqrtf(var + 1e-5f);

    int c = t * 4;
    float4 gg = reinterpret_cast<const float4*>(g)[t];
    float4 bb = reinterpret_cast<const float4*>(b)[t];
    float4 o;
    o.x = (v.x - mu) * inv * gg.x + bb.x;
    o.y = (v.y - mu) * inv * gg.y + bb.y;
    o.z = (v.z - mu) * inv * gg.z + bb.z;
    o.w = (v.w - mu) * inv * gg.w + bb.w;
    reinterpret_cast<float4*>(y + row * Ez)[t] = o;
    (void)c;
}

// ---------------- Softmax over rows of 2048 with 1/sqrt(E)=1/32 scale ----------------
__global__ __launch_bounds__(256) void softmax_k(float* __restrict__ S)
{
    __shared__ float sh[8];
    long long row = blockIdx.x;
    float* p = S + row * (long long)Lz;
    int t = threadIdx.x;
    const float scale = 1.f / 32.f;

    float4 v0 = reinterpret_cast<const float4*>(p)[t];
    float4 v1 = reinterpret_cast<const float4*>(p)[t + 256];

    float m = fmaxf(fmaxf(fmaxf(v0.x, v0.y), fmaxf(v0.z, v0.w)),
                    fmaxf(fmaxf(v1.x, v1.y), fmaxf(v1.z, v1.w)));
    #pragma unroll
    for (int o = 16; o > 0; o >>= 1) m = fmaxf(m, __shfl_down_sync(0xffffffffu, m, o));
    int warp = t >> 5, lane = t & 31;
    if (lane == 0) sh[warp] = m;
    __syncthreads();
    if (warp == 0) {
        m = (lane < 8) ? sh[lane] : -INFINITY;
        #pragma unroll
        for (int o = 4; o > 0; o >>= 1) m = fmaxf(m, __shfl_down_sync(0xffffffffu, m, o));
        if (lane == 0) sh[0] = m;
    }
    __syncthreads();
    m = sh[0];
    __syncthreads();

    v0.x = expf((v0.x - m) * scale); v0.y = expf((v0.y - m) * scale);
    v0.z = expf((v0.z - m) * scale); v0.w = expf((v0.w - m) * scale);
    v1.x = expf((v1.x - m) * scale); v1.y = expf((v1.y - m) * scale);
    v1.z = expf((v1.z - m) * scale); v1.w = expf((v1.w - m) * scale);

    float s = v0.x + v0.y + v0.z + v0.w + v1.x + v1.y + v1.z + v1.w;
    #pragma unroll
    for (int o = 16; o > 0; o >>= 1) s += __shfl_down_sync(0xffffffffu, s, o);
    if (lane == 0) sh[warp] = s;
    __syncthreads();
    if (warp == 0) {
        s = (lane < 8) ? sh[lane] : 0.f;
        #pragma unroll
        for (int o = 4; o > 0; o >>= 1) s += __shfl_down_sync(0xffffffffu, s, o);
        if (lane == 0) sh[0] = s;
    }
    __syncthreads();
    float r = 1.f / sh[0];

    v0.x *= r; v0.y *= r; v0.z *= r; v0.w *= r;
    v1.x *= r; v1.y *= r; v1.z *= r; v1.w *= r;
    reinterpret_cast<float4*>(p)[t]       = v0;
    reinterpret_cast<float4*>(p)[t + 256] = v1;
}

// ---------------- driver ----------------
extern "C" void kernel_launch(void* const* d_in, const int* in_sizes, int n_in,
                              void* d_out, int out_size)
{
    (void)in_sizes; (void)n_in; (void)out_size;
    const float* x      = (const float*)d_in[0];
    const float* ln1_g  = (const float*)d_in[1];
    const float* ln1_b  = (const float*)d_in[2];
    const float* W_qkv  = (const float*)d_in[3];
    const float* W_proj = (const float*)d_in[4];
    const float* b_proj = (const float*)d_in[5];
    const float* ln2_g  = (const float*)d_in[6];
    const float* ln2_b  = (const float*)d_in[7];
    const float* W1     = (const float*)d_in[8];
    const float* b1     = (const float*)d_in[9];
    const float* W2     = (const float*)d_in[10];
    const float* b2     = (const float*)d_in[11];
    float* out = (float*)d_out;

    float *h, *qkv, *S, *att, *x1, *ffn;
    cudaGetSymbolAddress((void**)&h,   g_h);
    cudaGetSymbolAddress((void**)&qkv, g_qkv);
    cudaGetSymbolAddress((void**)&S,   g_S);
    cudaGetSymbolAddress((void**)&att, g_att);
    cudaGetSymbolAddress((void**)&x1,  g_x1);
    cudaGetSymbolAddress((void**)&ffn, g_ffn);

    // 1. h = LN1(x)
    ln_k<<<BLz, 256>>>(x, ln1_g, ln1_b, h);

    // 2. qkv = h @ W_qkv              [4096,1024]x[1024,3072]
    gemm_k<false, EPI_NONE><<<dim3(E3z / 128, BLz / 128, 1), 256>>>(
        h, W_qkv, qkv, nullptr, nullptr,
        BLz, E3z, Ez, Ez, E3z, E3z, 1, 0, 0, 0, 0, 0, 0);

    // 3. S = Q @ K^T (batched over b,h)  M=N=2048, K=64
    gemm_k<true, EPI_NONE><<<dim3(Lz / 128, Lz / 128, Bz * Hz), 256>>>(
        qkv,            /* Q view */
        qkv + Ez,       /* K view */
        S, nullptr, nullptr,
        Lz, Lz, Dz, E3z, E3z, Lz, Hz,
        (long long)Lz * E3z, Dz,                 /* A strides (b,h) */
        (long long)Lz * E3z, Dz,                 /* B strides */
        (long long)Hz * Lz * Lz, (long long)Lz * Lz);

    // 4. softmax rows (scale 1/32 inside)
    softmax_k<<<Bz * Hz * Lz, 256>>>(S);

    // 5. att = P @ V  (batched) M=2048, N=64, K=2048; writes [B,L,E] layout
    gemm_k<false, EPI_NONE><<<dim3(1, Lz / 128, Bz * Hz), 256>>>(
        S, qkv + 2 * Ez, att, nullptr, nullptr,
        Lz, Dz, Lz, Lz, E3z, Ez, Hz,
        (long long)Hz * Lz * Lz, (long long)Lz * Lz,
        (long long)Lz * E3z, Dz,
        (long long)Lz * Ez, Dz);

    // 6. x1 = x + att @ W_proj + b_proj
    gemm_k<false, EPI_BIAS_RES><<<dim3(Ez / 128, BLz / 128, 1), 256>>>(
        att, W_proj, x1, b_proj, x,
        BLz, Ez, Ez, Ez, Ez, Ez, 1, 0, 0, 0, 0, 0, 0);

    // 7. h = LN2(x1)
    ln_k<<<BLz, 256>>>(x1, ln2_g, ln2_b, h);

    // 8. ffn = gelu(h @ W1 + b1)      [4096,1024]x[1024,4096]
    gemm_k<false, EPI_BIAS_GELU><<<dim3(FFz / 128, BLz / 128, 1), 256>>>(
        h, W1, ffn, b1, nullptr,
        BLz, FFz, Ez, Ez, FFz, FFz, 1, 0, 0, 0, 0, 0, 0);

    // 9. out = x1 + ffn @ W2 + b2     [4096,4096]x[4096,1024]
    gemm_k<false, EPI_BIAS_RES><<<dim3(Ez / 128, BLz / 128, 1), 256>>>(
        ffn, W2, out, b2, x1,
        BLz, Ez, FFz, FFz, Ez, Ez, 1, 0, 0, 0, 0, 0, 0);
}

// round 8
// speedup vs baseline: 2.5096x; 2.5096x over previous
#include <cuda_runtime.h>
#include <math.h>
#include <stdint.h>

// Problem constants
#define Bz   2
#define Lz   2048
#define Ez   1024
#define Hz   16
#define Dz   64
#define BLz  (Bz*Lz)          // 4096 rows
#define E3z  (3*Ez)           // 3072
#define FFz  (4*Ez)           // 4096

// ---------------- static device scratch (no allocations allowed) ----------------
__device__ float g_h    [(size_t)BLz*Ez];
__device__ float g_qkv  [(size_t)BLz*E3z];
__device__ float g_S    [(size_t)Bz*Hz*Lz*Lz];     // 512 MB scores
__device__ float g_att  [(size_t)BLz*Ez];
__device__ float g_x1   [(size_t)BLz*Ez];
__device__ float g_ffn  [(size_t)BLz*FFz];
__device__ float g_wqkvT[(size_t)E3z*Ez];
__device__ float g_wprojT[(size_t)Ez*Ez];
__device__ float g_w1T  [(size_t)FFz*Ez];
__device__ float g_w2T  [(size_t)Ez*FFz];
__device__ float g_vT   [(size_t)Bz*Hz*Dz*Lz];

// ---------------- helpers ----------------
static __device__ __forceinline__ float tf32r(float x) {
    uint32_t r;
    asm("cvt.rna.tf32.f32 %0, %1;" : "=r"(r) : "f"(x));
    return __uint_as_float(r);
}
static __device__ __forceinline__ void mma_tf32(
    float* c, const float* a, const float* b)
{
    asm volatile(
        "mma.sync.aligned.m16n8k8.row.col.f32.tf32.tf32.f32 "
        "{%0,%1,%2,%3}, {%4,%5,%6,%7}, {%8,%9}, {%0,%1,%2,%3};"
        : "+f"(c[0]), "+f"(c[1]), "+f"(c[2]), "+f"(c[3])
        : "r"(__float_as_uint(a[0])), "r"(__float_as_uint(a[1])),
          "r"(__float_as_uint(a[2])), "r"(__float_as_uint(a[3])),
          "r"(__float_as_uint(b[0])), "r"(__float_as_uint(b[1])));
}

// ---------------- tf32 mma.sync GEMM: 128 x BN tile, BK=32, 256 threads ----------------
// A: [M,K] K-major (lda), B: [N,K] K-major (ldb), C: [M,N] (ldc).
// M%128==0, N%BN==0, K%32==0 by construction of all call sites.
enum { EPI_NONE = 0, EPI_BIAS_RES = 1, EPI_BIAS_GELU = 2 };

#define SLD 36   // smem row stride in floats (conflict-free fragment reads)

template<int BN, int EPI>
__global__ void __launch_bounds__(256, 1)
mma_gemm(const float* __restrict__ A, const float* __restrict__ B, float* __restrict__ C,
         const float* __restrict__ bias, const float* __restrict__ res,
         int K, int lda, int ldb, int ldc, int NH,
         long long sAb, long long sAh, long long sBb, long long sBh,
         long long sCb, long long sCh)
{
    constexpr int WN  = BN / 4;       // warp n-extent (32 or 16)
    constexpr int NT  = WN / 8;       // n-tiles per warp (4 or 2)
    constexpr int PBn = BN / 32;      // B prefetch float4s per thread

    __shared__ float As[128][SLD];
    __shared__ float Bs[BN][SLD];

    int tid  = threadIdx.x;
    int lane = tid & 31;
    int wid  = tid >> 5;
    int warp_m = wid & 1;             // 2 warps along m (WM=64)
    int warp_n = wid >> 1;            // 4 warps along n

    int z = blockIdx.z;
    int bb = z / NH, hh = z % NH;
    A += bb * sAb + hh * sAh;
    B += bb * sBb + hh * sBh;
    C += bb * sCb + hh * sCh;
    const float* resp = (EPI == EPI_BIAS_RES) ? (res + bb * sCb + hh * sCh) : res;

    int m0 = blockIdx.y * 128;
    int n0 = blockIdx.x * BN;

    float acc[4][NT][4];
    #pragma unroll
    for (int i = 0; i < 4; i++)
        #pragma unroll
        for (int j = 0; j < NT; j++)
            #pragma unroll
            for (int k = 0; k < 4; k++) acc[i][j][k] = 0.f;

    const int slabs = K >> 5;
    float4 pa[4], pb[PBn];

    // prefetch slab 0
    #pragma unroll
    for (int i = 0; i < 4; i++) {
        int e = tid + i * 256, row = e >> 3, c4 = e & 7;
        pa[i] = *reinterpret_cast<const float4*>(&A[(long long)(m0 + row) * lda + c4 * 4]);
    }
    #pragma unroll
    for (int i = 0; i < PBn; i++) {
        int e = tid + i * 256, row = e >> 3, c4 = e & 7;
        pb[i] = *reinterpret_cast<const float4*>(&B[(long long)(n0 + row) * ldb + c4 * 4]);
    }

    for (int s = 0; s < slabs; s++) {
        // store prefetched slab to smem with RN tf32 rounding
        #pragma unroll
        for (int i = 0; i < 4; i++) {
            int e = tid + i * 256, row = e >> 3, c4 = e & 7;
            float4 u = make_float4(tf32r(pa[i].x), tf32r(pa[i].y),
                                   tf32r(pa[i].z), tf32r(pa[i].w));
            *reinterpret_cast<float4*>(&As[row][c4 * 4]) = u;
        }
        #pragma unroll
        for (int i = 0; i < PBn; i++) {
            int e = tid + i * 256, row = e >> 3, c4 = e & 7;
            float4 u = make_float4(tf32r(pb[i].x), tf32r(pb[i].y),
                                   tf32r(pb[i].z), tf32r(pb[i].w));
            *reinterpret_cast<float4*>(&Bs[row][c4 * 4]) = u;
        }
        __syncthreads();

        // prefetch next slab while computing this one
        if (s + 1 < slabs) {
            int k0 = (s + 1) << 5;
            #pragma unroll
            for (int i = 0; i < 4; i++) {
                int e = tid + i * 256, row = e >> 3, c4 = e & 7;
                pa[i] = *reinterpret_cast<const float4*>(
                    &A[(long long)(m0 + row) * lda + k0 + c4 * 4]);
            }
            #pragma unroll
            for (int i = 0; i < PBn; i++) {
                int e = tid + i * 256, row = e >> 3, c4 = e & 7;
                pb[i] = *reinterpret_cast<const float4*>(
                    &B[(long long)(n0 + row) * ldb + k0 + c4 * 4]);
            }
        }

        int qr = lane >> 2, qc = lane & 3;
        #pragma unroll
        for (int ks = 0; ks < 4; ks++) {
            int kk = ks * 8;
            float af[4][4];
            #pragma unroll
            for (int mt = 0; mt < 4; mt++) {
                int r = warp_m * 64 + mt * 16 + qr;
                af[mt][0] = As[r    ][kk + qc];
                af[mt][1] = As[r + 8][kk + qc];
                af[mt][2] = As[r    ][kk + 4 + qc];
                af[mt][3] = As[r + 8][kk + 4 + qc];
            }
            float bf[NT][2];
            #pragma unroll
            for (int nt = 0; nt < NT; nt++) {
                int cN = warp_n * WN + nt * 8 + qr;
                bf[nt][0] = Bs[cN][kk + qc];
                bf[nt][1] = Bs[cN][kk + 4 + qc];
            }
            #pragma unroll
            for (int mt = 0; mt < 4; mt++)
                #pragma unroll
                for (int nt = 0; nt < NT; nt++)
                    mma_tf32(acc[mt][nt], af[mt], bf[nt]);
        }
        __syncthreads();
    }

    // ---------------- epilogue: direct f32x2 stores ----------------
    int qr = lane >> 2, qc = lane & 3;
    #pragma unroll
    for (int mt = 0; mt < 4; mt++) {
        #pragma unroll
        for (int nt = 0; nt < NT; nt++) {
            int gc = n0 + warp_n * WN + nt * 8 + qc * 2;
            #pragma unroll
            for (int half = 0; half < 2; half++) {
                long long gr = m0 + warp_m * 64 + mt * 16 + qr + half * 8;
                float v0 = acc[mt][nt][half * 2 + 0];
                float v1 = acc[mt][nt][half * 2 + 1];
                if (EPI == EPI_BIAS_RES) {
                    v0 += bias[gc]     + resp[gr * ldc + gc];
                    v1 += bias[gc + 1] + resp[gr * ldc + gc + 1];
                }
                if (EPI == EPI_BIAS_GELU) {
                    v0 += bias[gc];
                    v1 += bias[gc + 1];
                    v0 = 0.5f * v0 * (1.f + erff(v0 * 0.70710678118654752f));
                    v1 = 0.5f * v1 * (1.f + erff(v1 * 0.70710678118654752f));
                }
                *reinterpret_cast<float2*>(&C[gr * ldc + gc]) = make_float2(v0, v1);
            }
        }
    }
}

// ---------------- tiled transpose: dst[c][r] = src[r][c] (dims % 32 == 0) ----------------
__global__ void __launch_bounds__(256) transpose_k(
    const float* __restrict__ src, float* __restrict__ dst,
    int lds, int ldd, int NH,
    long long sSb, long long sSh, long long sDb, long long sDh)
{
    __shared__ float t[32][33];
    int z = blockIdx.z, bb = z / NH, hh = z % NH;
    src += bb * sSb + hh * sSh;
    dst += bb * sDb + hh * sDh;
    int r0 = blockIdx.y * 32, c0 = blockIdx.x * 32;
    int x = threadIdx.x & 31, y4 = (threadIdx.x >> 5) * 4;
    #pragma unroll
    for (int i = 0; i < 4; i++)
        t[y4 + i][x] = src[(long long)(r0 + y4 + i) * lds + c0 + x];
    __syncthreads();
    #pragma unroll
    for (int i = 0; i < 4; i++)
        dst[(long long)(c0 + y4 + i) * ldd + r0 + x] = t[x][y4 + i];
}

// ---------------- LayerNorm: one block per row of E=1024 ----------------
__global__ __launch_bounds__(256) void ln_k(
    const float* __restrict__ x, const float* __restrict__ g,
    const float* __restrict__ b, float* __restrict__ y)
{
    __shared__ float sh_s[8];
    __shared__ float sh_q[8];
    long long row = blockIdx.x;
    const float* xr = x + row * Ez;
    int t = threadIdx.x;

    float4 v = reinterpret_cast<const float4*>(xr)[t];
    float s  = v.x + v.y + v.z + v.w;
    float sq = v.x * v.x + v.y * v.y + v.z * v.z + v.w * v.w;
    #pragma unroll
    for (int o = 16; o > 0; o >>= 1) {
        s  += __shfl_down_sync(0xffffffffu, s,  o);
        sq += __shfl_down_sync(0xffffffffu, sq, o);
    }
    int warp = t >> 5, lane = t & 31;
    if (lane == 0) { sh_s[warp] = s; sh_q[warp] = sq; }
    __syncthreads();
    if (warp == 0) {
        s  = (lane < 8) ? sh_s[lane] : 0.f;
        sq = (lane < 8) ? sh_q[lane] : 0.f;
        #pragma unroll
        for (int o = 4; o > 0; o >>= 1) {
            s  += __shfl_down_sync(0xffffffffu, s,  o);
            sq += __shfl_down_sync(0xffffffffu, sq, o);
        }
        if (lane == 0) { sh_s[0] = s; sh_q[0] = sq; }
    }
    __syncthreads();
    float mu  = sh_s[0] * (1.f / Ez);
    float var = sh_q[0] * (1.f / Ez) - mu * mu;
    float inv = rsqrtf(var + 1e-5f);

    float4 gg = reinterpret_cast<const float4*>(g)[t];
    float4 bb = reinterpret_cast<const float4*>(b)[t];
    float4 o;
    o.x = (v.x - mu) * inv * gg.x + bb.x;
    o.y = (v.y - mu) * inv * gg.y + bb.y;
    o.z = (v.z - mu) * inv * gg.z + bb.z;
    o.w = (v.w - mu) * inv * gg.w + bb.w;
    reinterpret_cast<float4*>(y + row * Ez)[t] = o;
}

// ---------------- Softmax over rows of 2048 with 1/sqrt(E)=1/32 scale ----------------
__global__ __launch_bounds__(256) void softmax_k(float* __restrict__ S)
{
    __shared__ float sh[8];
    long long row = blockIdx.x;
    float* p = S + row * (long long)Lz;
    int t = threadIdx.x;
    const float scale = 1.f / 32.f;

    float4 v0 = reinterpret_cast<const float4*>(p)[t];
    float4 v1 = reinterpret_cast<const float4*>(p)[t + 256];

    float m = fmaxf(fmaxf(fmaxf(v0.x, v0.y), fmaxf(v0.z, v0.w)),
                    fmaxf(fmaxf(v1.x, v1.y), fmaxf(v1.z, v1.w)));
    #pragma unroll
    for (int o = 16; o > 0; o >>= 1) m = fmaxf(m, __shfl_down_sync(0xffffffffu, m, o));
    int warp = t >> 5, lane = t & 31;
    if (lane == 0) sh[warp] = m;
    __syncthreads();
    if (warp == 0) {
        m = (lane < 8) ? sh[lane] : -INFINITY;
        #pragma unroll
        for (int o = 4; o > 0; o >>= 1) m = fmaxf(m, __shfl_down_sync(0xffffffffu, m, o));
        if (lane == 0) sh[0] = m;
    }
    __syncthreads();
    m = sh[0];
    __syncthreads();

    v0.x = expf((v0.x - m) * scale); v0.y = expf((v0.y - m) * scale);
    v0.z = expf((v0.z - m) * scale); v0.w = expf((v0.w - m) * scale);
    v1.x = expf((v1.x - m) * scale); v1.y = expf((v1.y - m) * scale);
    v1.z = expf((v1.z - m) * scale); v1.w = expf((v1.w - m) * scale);

    float s = v0.x + v0.y + v0.z + v0.w + v1.x + v1.y + v1.z + v1.w;
    #pragma unroll
    for (int o = 16; o > 0; o >>= 1) s += __shfl_down_sync(0xffffffffu, s, o);
    if (lane == 0) sh[warp] = s;
    __syncthreads();
    if (warp == 0) {
        s = (lane < 8) ? sh[lane] : 0.f;
        #pragma unroll
        for (int o = 4; o > 0; o >>= 1) s += __shfl_down_sync(0xffffffffu, s, o);
        if (lane == 0) sh[0] = s;
    }
    __syncthreads();
    float r = 1.f / sh[0];

    v0.x *= r; v0.y *= r; v0.z *= r; v0.w *= r;
    v1.x *= r; v1.y *= r; v1.z *= r; v1.w *= r;
    reinterpret_cast<float4*>(p)[t]       = v0;
    reinterpret_cast<float4*>(p)[t + 256] = v1;
}

// ---------------- driver ----------------
extern "C" void kernel_launch(void* const* d_in, const int* in_sizes, int n_in,
                              void* d_out, int out_size)
{
    (void)in_sizes; (void)n_in; (void)out_size;
    const float* x      = (const float*)d_in[0];
    const float* ln1_g  = (const float*)d_in[1];
    const float* ln1_b  = (const float*)d_in[2];
    const float* W_qkv  = (const float*)d_in[3];
    const float* W_proj = (const float*)d_in[4];
    const float* b_proj = (const float*)d_in[5];
    const float* ln2_g  = (const float*)d_in[6];
    const float* ln2_b  = (const float*)d_in[7];
    const float* W1     = (const float*)d_in[8];
    const float* b1     = (const float*)d_in[9];
    const float* W2     = (const float*)d_in[10];
    const float* b2     = (const float*)d_in[11];
    float* out = (float*)d_out;

    float *h, *qkv, *S, *att, *x1, *ffn, *wqkvT, *wprojT, *w1T, *w2T, *vT;
    cudaGetSymbolAddress((void**)&h,      g_h);
    cudaGetSymbolAddress((void**)&qkv,    g_qkv);
    cudaGetSymbolAddress((void**)&S,      g_S);
    cudaGetSymbolAddress((void**)&att,    g_att);
    cudaGetSymbolAddress((void**)&x1,     g_x1);
    cudaGetSymbolAddress((void**)&ffn,    g_ffn);
    cudaGetSymbolAddress((void**)&wqkvT,  g_wqkvT);
    cudaGetSymbolAddress((void**)&wprojT, g_wprojT);
    cudaGetSymbolAddress((void**)&w1T,    g_w1T);
    cudaGetSymbolAddress((void**)&w2T,    g_w2T);
    cudaGetSymbolAddress((void**)&vT,     g_vT);

    // 1. h = LN1(x)
    ln_k<<<BLz, 256>>>(x, ln1_g, ln1_b, h);

    // 2. one-shot weight transposes -> [N][K] K-major operands
    transpose_k<<<dim3(E3z / 32, Ez / 32, 1), 256>>>(W_qkv,  wqkvT,  E3z, Ez,  1, 0, 0, 0, 0);
    transpose_k<<<dim3(Ez  / 32, Ez / 32, 1), 256>>>(W_proj, wprojT, Ez,  Ez,  1, 0, 0, 0, 0);
    transpose_k<<<dim3(FFz / 32, Ez / 32, 1), 256>>>(W1,     w1T,    FFz, Ez,  1, 0, 0, 0, 0);
    transpose_k<<<dim3(Ez  / 32, FFz / 32, 1), 256>>>(W2,    w2T,    Ez,  FFz, 1, 0, 0, 0, 0);

    // 3. qkv = h @ W_qkv     [4096,1024] x [1024,3072]
    mma_gemm<128, EPI_NONE><<<dim3(E3z / 128, BLz / 128, 1), 256>>>(
        h, wqkvT, qkv, nullptr, nullptr,
        Ez, Ez, Ez, E3z, 1, 0, 0, 0, 0, 0, 0);

    // 4. vT[b,h] = V[b,h]^T  ([D][L] per head)
    transpose_k<<<dim3(Dz / 32, Lz / 32, Bz * Hz), 256>>>(
        qkv + 2 * Ez, vT, E3z, Lz, Hz,
        (long long)Lz * E3z, Dz,
        (long long)Hz * Dz * Lz, (long long)Dz * Lz);

    // 5. S = Q @ K^T (batched)  M=N=2048, K=64
    mma_gemm<128, EPI_NONE><<<dim3(Lz / 128, Lz / 128, Bz * Hz), 256>>>(
        qkv, qkv + Ez, S, nullptr, nullptr,
        Dz, E3z, E3z, Lz, Hz,
        (long long)Lz * E3z, Dz,
        (long long)Lz * E3z, Dz,
        (long long)Hz * Lz * Lz, (long long)Lz * Lz);

    // 6. softmax rows (scale 1/32 inside)
    softmax_k<<<Bz * Hz * Lz, 256>>>(S);

    // 7. att = P @ V (batched)  M=2048, N=64, K=2048; writes [B,L,E]
    mma_gemm<64, EPI_NONE><<<dim3(1, Lz / 128, Bz * Hz), 256>>>(
        S, vT, att, nullptr, nullptr,
        Lz, Lz, Lz, Ez, Hz,
        (long long)Hz * Lz * Lz, (long long)Lz * Lz,
        (long long)Hz * Dz * Lz, (long long)Dz * Lz,
        (long long)Lz * Ez, Dz);

    // 8. x1 = x + att @ W_proj + b_proj
    mma_gemm<128, EPI_BIAS_RES><<<dim3(Ez / 128, BLz / 128, 1), 256>>>(
        att, wprojT, x1, b_proj, x,
        Ez, Ez, Ez, Ez, 1, 0, 0, 0, 0, 0, 0);

    // 9. h = LN2(x1)
    ln_k<<<BLz, 256>>>(x1, ln2_g, ln2_b, h);

    // 10. ffn = gelu(h @ W1 + b1)
    mma_gemm<128, EPI_BIAS_GELU><<<dim3(FFz / 128, BLz / 128, 1), 256>>>(
        h, w1T, ffn, b1, nullptr,
        Ez, Ez, Ez, FFz, 1, 0, 0, 0, 0, 0, 0);

    // 11. out = x1 + ffn @ W2 + b2
    mma_gemm<128, EPI_BIAS_RES><<<dim3(Ez / 128, BLz / 128, 1), 256>>>(
        ffn, w2T, out, b2, x1,
        FFz, FFz, FFz, Ez, 1, 0, 0, 0, 0, 0, 0);
}

// round 9
// speedup vs baseline: 3.1069x; 1.2380x over previous
#include <cuda_runtime.h>
#include <math.h>
#include <stdint.h>

// Problem constants
#define Bz   2
#define Lz   2048
#define Ez   1024
#define Hz   16
#define Dz   64
#define BLz  (Bz*Lz)          // 4096 rows
#define E3z  (3*Ez)           // 3072
#define FFz  (4*Ez)           // 4096

// ---------------- static device scratch (no allocations allowed) ----------------
__device__ float g_h    [(size_t)BLz*Ez];
__device__ float g_qkv  [(size_t)BLz*E3z];
__device__ float g_att  [(size_t)BLz*Ez];
__device__ float g_x1   [(size_t)BLz*Ez];
__device__ float g_ffn  [(size_t)BLz*FFz];
__device__ float g_wqkvT[(size_t)E3z*Ez];
__device__ float g_wprojT[(size_t)Ez*Ez];
__device__ float g_w1T  [(size_t)FFz*Ez];
__device__ float g_w2T  [(size_t)Ez*FFz];
__device__ float g_vT   [(size_t)Bz*Hz*Dz*Lz];

// ---------------- helpers ----------------
static __device__ __forceinline__ float tf32r(float x) {
    uint32_t r;
    asm("cvt.rna.tf32.f32 %0, %1;" : "=r"(r) : "f"(x));
    return __uint_as_float(r);
}
static __device__ __forceinline__ void mma_tf32(
    float* c, const float* a, const float* b)
{
    asm volatile(
        "mma.sync.aligned.m16n8k8.row.col.f32.tf32.tf32.f32 "
        "{%0,%1,%2,%3}, {%4,%5,%6,%7}, {%8,%9}, {%0,%1,%2,%3};"
        : "+f"(c[0]), "+f"(c[1]), "+f"(c[2]), "+f"(c[3])
        : "r"(__float_as_uint(a[0])), "r"(__float_as_uint(a[1])),
          "r"(__float_as_uint(a[2])), "r"(__float_as_uint(a[3])),
          "r"(__float_as_uint(b[0])), "r"(__float_as_uint(b[1])));
}

// ---------------- tf32 mma.sync GEMM: 128 x BN tile, BK=32, 256 threads ----------------
enum { EPI_NONE = 0, EPI_BIAS_RES = 1, EPI_BIAS_GELU = 2 };

#define SLD 36   // smem row stride in floats (conflict-free fragment reads)

template<int BN, int EPI>
__global__ void __launch_bounds__(256, 1)
mma_gemm(const float* __restrict__ A, const float* __restrict__ B, float* __restrict__ C,
         const float* __restrict__ bias, const float* __restrict__ res,
         int K, int lda, int ldb, int ldc, int NH,
         long long sAb, long long sAh, long long sBb, long long sBh,
         long long sCb, long long sCh)
{
    constexpr int WN  = BN / 4;
    constexpr int NT  = WN / 8;
    constexpr int PBn = BN / 32;

    __shared__ float As[128][SLD];
    __shared__ float Bs[BN][SLD];

    int tid  = threadIdx.x;
    int lane = tid & 31;
    int wid  = tid >> 5;
    int warp_m = wid & 1;
    int warp_n = wid >> 1;

    int z = blockIdx.z;
    int bb = z / NH, hh = z % NH;
    A += bb * sAb + hh * sAh;
    B += bb * sBb + hh * sBh;
    C += bb * sCb + hh * sCh;
    const float* resp = (EPI == EPI_BIAS_RES) ? (res + bb * sCb + hh * sCh) : res;

    int m0 = blockIdx.y * 128;
    int n0 = blockIdx.x * BN;

    float acc[4][NT][4];
    #pragma unroll
    for (int i = 0; i < 4; i++)
        #pragma unroll
        for (int j = 0; j < NT; j++)
            #pragma unroll
            for (int k = 0; k < 4; k++) acc[i][j][k] = 0.f;

    const int slabs = K >> 5;
    float4 pa[4], pb[PBn];

    #pragma unroll
    for (int i = 0; i < 4; i++) {
        int e = tid + i * 256, row = e >> 3, c4 = e & 7;
        pa[i] = *reinterpret_cast<const float4*>(&A[(long long)(m0 + row) * lda + c4 * 4]);
    }
    #pragma unroll
    for (int i = 0; i < PBn; i++) {
        int e = tid + i * 256, row = e >> 3, c4 = e & 7;
        pb[i] = *reinterpret_cast<const float4*>(&B[(long long)(n0 + row) * ldb + c4 * 4]);
    }

    for (int s = 0; s < slabs; s++) {
        #pragma unroll
        for (int i = 0; i < 4; i++) {
            int e = tid + i * 256, row = e >> 3, c4 = e & 7;
            float4 u = make_float4(tf32r(pa[i].x), tf32r(pa[i].y),
                                   tf32r(pa[i].z), tf32r(pa[i].w));
            *reinterpret_cast<float4*>(&As[row][c4 * 4]) = u;
        }
        #pragma unroll
        for (int i = 0; i < PBn; i++) {
            int e = tid + i * 256, row = e >> 3, c4 = e & 7;
            float4 u = make_float4(tf32r(pb[i].x), tf32r(pb[i].y),
                                   tf32r(pb[i].z), tf32r(pb[i].w));
            *reinterpret_cast<float4*>(&Bs[row][c4 * 4]) = u;
        }
        __syncthreads();

        if (s + 1 < slabs) {
            int k0 = (s + 1) << 5;
            #pragma unroll
            for (int i = 0; i < 4; i++) {
                int e = tid + i * 256, row = e >> 3, c4 = e & 7;
                pa[i] = *reinterpret_cast<const float4*>(
                    &A[(long long)(m0 + row) * lda + k0 + c4 * 4]);
            }
            #pragma unroll
            for (int i = 0; i < PBn; i++) {
                int e = tid + i * 256, row = e >> 3, c4 = e & 7;
                pb[i] = *reinterpret_cast<const float4*>(
                    &B[(long long)(n0 + row) * ldb + k0 + c4 * 4]);
            }
        }

        int qr = lane >> 2, qc = lane & 3;
        #pragma unroll
        for (int ks = 0; ks < 4; ks++) {
            int kk = ks * 8;
            float af[4][4];
            #pragma unroll
            for (int mt = 0; mt < 4; mt++) {
                int r = warp_m * 64 + mt * 16 + qr;
                af[mt][0] = As[r    ][kk + qc];
                af[mt][1] = As[r + 8][kk + qc];
                af[mt][2] = As[r    ][kk + 4 + qc];
                af[mt][3] = As[r + 8][kk + 4 + qc];
            }
            float bf[NT][2];
            #pragma unroll
            for (int nt = 0; nt < NT; nt++) {
                int cN = warp_n * WN + nt * 8 + qr;
                bf[nt][0] = Bs[cN][kk + qc];
                bf[nt][1] = Bs[cN][kk + 4 + qc];
            }
            #pragma unroll
            for (int mt = 0; mt < 4; mt++)
                #pragma unroll
                for (int nt = 0; nt < NT; nt++)
                    mma_tf32(acc[mt][nt], af[mt], bf[nt]);
        }
        __syncthreads();
    }

    int qr = lane >> 2, qc = lane & 3;
    #pragma unroll
    for (int mt = 0; mt < 4; mt++) {
        #pragma unroll
        for (int nt = 0; nt < NT; nt++) {
            int gc = n0 + warp_n * WN + nt * 8 + qc * 2;
            #pragma unroll
            for (int half = 0; half < 2; half++) {
                long long gr = m0 + warp_m * 64 + mt * 16 + qr + half * 8;
                float v0 = acc[mt][nt][half * 2 + 0];
                float v1 = acc[mt][nt][half * 2 + 1];
                if (EPI == EPI_BIAS_RES) {
                    v0 += bias[gc]     + resp[gr * ldc + gc];
                    v1 += bias[gc + 1] + resp[gr * ldc + gc + 1];
                }
                if (EPI == EPI_BIAS_GELU) {
                    v0 += bias[gc];
                    v1 += bias[gc + 1];
                    v0 = 0.5f * v0 * (1.f + erff(v0 * 0.70710678118654752f));
                    v1 = 0.5f * v1 * (1.f + erff(v1 * 0.70710678118654752f));
                }
                *reinterpret_cast<float2*>(&C[gr * ldc + gc]) = make_float2(v0, v1);
            }
        }
    }
}

// ---------------- fused flash attention ----------------
// Grid: (Lz/128, Bz*Hz). 256 threads. One CTA = one (head, 128-query tile).
// Q/K from g_qkv (K-major, stride E3z), V from g_vT ([D][L] per head).
// Computes att[B,L,E] = softmax(Q K^T / 32) V for its tile.
#define QLD 68    // Q/K smem stride  (68 % 32 == 4)
#define VLD 132   // V/S smem stride  (132 % 32 == 4)

__global__ void __launch_bounds__(256, 1)
flash_k(const float* __restrict__ qkv, const float* __restrict__ vT,
        float* __restrict__ att)
{
    extern __shared__ float sm[];
    float* Qs   = sm;                    // 128 x QLD
    float* Ks   = Qs + 128 * QLD;        // 128 x QLD
    float* Vs   = Ks + 128 * QLD;        // 64  x VLD  (dim-major: Vs[d][key])
    float* Ss   = Vs + 64 * VLD;         // 128 x VLD
    float* rowm = Ss + 128 * VLD;        // 128
    float* rowl = rowm + 128;            // 128
    float* rowf = rowl + 128;            // 128

    int tid  = threadIdx.x;
    int lane = tid & 31;
    int wid  = tid >> 5;
    int qr = lane >> 2, qc = lane & 3;
    int warp_m = wid >> 1;               // 0..3 : 32 query rows each
    int warp_n = wid & 1;                // 0..1 : QK cols 64 each, PV cols 32 each

    int bb = blockIdx.y >> 4;            // Hz = 16
    int hh = blockIdx.y & 15;
    int q0 = blockIdx.x * 128;
    const float CEXP = 1.4426950408889634f / 32.f;   // log2(e)/sqrt(E)

    const float* Qg = qkv + (size_t)bb * Lz * E3z + hh * Dz;
    const float* Kg = qkv + (size_t)bb * Lz * E3z + Ez + hh * Dz;
    const float* Vg = vT + ((size_t)(bb * Hz + hh)) * Dz * Lz;

    // load Q tile (128 x 64), tf32-rounded
    #pragma unroll
    for (int i = 0; i < 8; i++) {
        int e = tid + i * 256, row = e >> 4, c4 = e & 15;
        float4 v = *reinterpret_cast<const float4*>(&Qg[(size_t)(q0 + row) * E3z + c4 * 4]);
        float4 u = make_float4(tf32r(v.x), tf32r(v.y), tf32r(v.z), tf32r(v.w));
        *reinterpret_cast<float4*>(&Qs[row * QLD + c4 * 4]) = u;
    }
    if (tid < 128) { rowm[tid] = -INFINITY; rowl[tid] = 0.f; }

    float o[2][4][4];
    #pragma unroll
    for (int mt = 0; mt < 2; mt++)
        #pragma unroll
        for (int nt = 0; nt < 4; nt++)
            #pragma unroll
            for (int k = 0; k < 4; k++) o[mt][nt][k] = 0.f;

    for (int kt = 0; kt < 16; kt++) {
        __syncthreads();    // prev PV reads of Ks/Vs/Ss done; Q visible on iter 0

        // fill K tile (128 keys x 64 dims)
        #pragma unroll
        for (int i = 0; i < 8; i++) {
            int e = tid + i * 256, row = e >> 4, c4 = e & 15;
            float4 v = *reinterpret_cast<const float4*>(
                &Kg[(size_t)(kt * 128 + row) * E3z + c4 * 4]);
            float4 u = make_float4(tf32r(v.x), tf32r(v.y), tf32r(v.z), tf32r(v.w));
            *reinterpret_cast<float4*>(&Ks[row * QLD + c4 * 4]) = u;
        }
        // fill V tile (64 dims x 128 keys), dim-major from vT
        #pragma unroll
        for (int i = 0; i < 8; i++) {
            int e = tid + i * 256, row = e >> 5, c4 = e & 31;
            float4 v = *reinterpret_cast<const float4*>(
                &Vg[(size_t)row * Lz + kt * 128 + c4 * 4]);
            float4 u = make_float4(tf32r(v.x), tf32r(v.y), tf32r(v.z), tf32r(v.w));
            *reinterpret_cast<float4*>(&Vs[row * VLD + c4 * 4]) = u;
        }
        __syncthreads();

        // ---- S = Q @ K^T (this warp: 32 rows x 64 cols) ----
        float sqk[2][8][4];
        #pragma unroll
        for (int mt = 0; mt < 2; mt++)
            #pragma unroll
            for (int nt = 0; nt < 8; nt++)
                #pragma unroll
                for (int k = 0; k < 4; k++) sqk[mt][nt][k] = 0.f;

        #pragma unroll
        for (int ks = 0; ks < 8; ks++) {
            int kk = ks * 8;
            float af[2][4];
            #pragma unroll
            for (int mt = 0; mt < 2; mt++) {
                int r = warp_m * 32 + mt * 16 + qr;
                af[mt][0] = Qs[r * QLD + kk + qc];
                af[mt][1] = Qs[(r + 8) * QLD + kk + qc];
                af[mt][2] = Qs[r * QLD + kk + 4 + qc];
                af[mt][3] = Qs[(r + 8) * QLD + kk + 4 + qc];
            }
            float bf[8][2];
            #pragma unroll
            for (int nt = 0; nt < 8; nt++) {
                int cN = warp_n * 64 + nt * 8 + qr;
                bf[nt][0] = Ks[cN * QLD + kk + qc];
                bf[nt][1] = Ks[cN * QLD + kk + 4 + qc];
            }
            #pragma unroll
            for (int mt = 0; mt < 2; mt++)
                #pragma unroll
                for (int nt = 0; nt < 8; nt++)
                    mma_tf32(sqk[mt][nt], af[mt], bf[nt]);
        }
        // spill S fragments to smem
        #pragma unroll
        for (int mt = 0; mt < 2; mt++) {
            int r = warp_m * 32 + mt * 16 + qr;
            #pragma unroll
            for (int nt = 0; nt < 8; nt++) {
                int c = warp_n * 64 + nt * 8 + qc * 2;
                Ss[r * VLD + c]           = sqk[mt][nt][0];
                Ss[r * VLD + c + 1]       = sqk[mt][nt][1];
                Ss[(r + 8) * VLD + c]     = sqk[mt][nt][2];
                Ss[(r + 8) * VLD + c + 1] = sqk[mt][nt][3];
            }
        }
        __syncthreads();

        // ---- online softmax row pass: 2 threads per row ----
        {
            int row = tid >> 1, half = tid & 1;
            float* p = &Ss[row * VLD + half * 64];
            float4 v[16];
            float mx = -INFINITY;
            #pragma unroll
            for (int j = 0; j < 16; j++) {
                v[j] = *reinterpret_cast<const float4*>(&p[j * 4]);
                mx = fmaxf(mx, fmaxf(fmaxf(v[j].x, v[j].y), fmaxf(v[j].z, v[j].w)));
            }
            mx = fmaxf(mx, __shfl_xor_sync(0xffffffffu, mx, 1));
            float mold = rowm[row];
            float mnew = fmaxf(mold, mx);
            float sum = 0.f;
            #pragma unroll
            for (int j = 0; j < 16; j++) {
                float e0 = exp2f((v[j].x - mnew) * CEXP);
                float e1 = exp2f((v[j].y - mnew) * CEXP);
                float e2 = exp2f((v[j].z - mnew) * CEXP);
                float e3 = exp2f((v[j].w - mnew) * CEXP);
                sum += (e0 + e1) + (e2 + e3);
                float4 u = make_float4(tf32r(e0), tf32r(e1), tf32r(e2), tf32r(e3));
                *reinterpret_cast<float4*>(&p[j * 4]) = u;
            }
            sum += __shfl_xor_sync(0xffffffffu, sum, 1);
            if (half == 0) {
                float f = exp2f((mold - mnew) * CEXP);
                rowm[row] = mnew;
                rowl[row] = rowl[row] * f + sum;
                rowf[row] = f;
            }
        }
        __syncthreads();

        // ---- rescale O, then O += P @ V (this warp: 32 rows x 32 dims) ----
        #pragma unroll
        for (int mt = 0; mt < 2; mt++) {
            int r = warp_m * 32 + mt * 16 + qr;
            float f0 = rowf[r], f8 = rowf[r + 8];
            #pragma unroll
            for (int nt = 0; nt < 4; nt++) {
                o[mt][nt][0] *= f0; o[mt][nt][1] *= f0;
                o[mt][nt][2] *= f8; o[mt][nt][3] *= f8;
            }
        }
        #pragma unroll
        for (int ks = 0; ks < 16; ks++) {
            int kk = ks * 8;
            float af[2][4];
            #pragma unroll
            for (int mt = 0; mt < 2; mt++) {
                int r = warp_m * 32 + mt * 16 + qr;
                af[mt][0] = Ss[r * VLD + kk + qc];
                af[mt][1] = Ss[(r + 8) * VLD + kk + qc];
                af[mt][2] = Ss[r * VLD + kk + 4 + qc];
                af[mt][3] = Ss[(r + 8) * VLD + kk + 4 + qc];
            }
            float bf[4][2];
            #pragma unroll
            for (int nt = 0; nt < 4; nt++) {
                int cN = warp_n * 32 + nt * 8 + qr;
                bf[nt][0] = Vs[cN * VLD + kk + qc];
                bf[nt][1] = Vs[cN * VLD + kk + 4 + qc];
            }
            #pragma unroll
            for (int mt = 0; mt < 2; mt++)
                #pragma unroll
                for (int nt = 0; nt < 4; nt++)
                    mma_tf32(o[mt][nt], af[mt], bf[nt]);
        }
    }

    // ---- finalize: divide by l and store to att[B,L,E] ----
    #pragma unroll
    for (int mt = 0; mt < 2; mt++) {
        int r = warp_m * 32 + mt * 16 + qr;
        float inv0 = 1.f / rowl[r];
        float inv8 = 1.f / rowl[r + 8];
        #pragma unroll
        for (int nt = 0; nt < 4; nt++) {
            int col = hh * Dz + warp_n * 32 + nt * 8 + qc * 2;
            size_t gr0 = (size_t)bb * Lz + q0 + r;
            *reinterpret_cast<float2*>(&att[gr0 * Ez + col]) =
                make_float2(o[mt][nt][0] * inv0, o[mt][nt][1] * inv0);
            *reinterpret_cast<float2*>(&att[(gr0 + 8) * Ez + col]) =
                make_float2(o[mt][nt][2] * inv8, o[mt][nt][3] * inv8);
        }
    }
}

// ---------------- tiled transpose: dst[c][r] = src[r][c] (dims % 32 == 0) ----------------
__global__ void __launch_bounds__(256) transpose_k(
    const float* __restrict__ src, float* __restrict__ dst,
    int lds, int ldd, int NH,
    long long sSb, long long sSh, long long sDb, long long sDh)
{
    __shared__ float t[32][33];
    int z = blockIdx.z, bb = z / NH, hh = z % NH;
    src += bb * sSb + hh * sSh;
    dst += bb * sDb + hh * sDh;
    int r0 = blockIdx.y * 32, c0 = blockIdx.x * 32;
    int x = threadIdx.x & 31, y4 = (threadIdx.x >> 5) * 4;
    #pragma unroll
    for (int i = 0; i < 4; i++)
        t[y4 + i][x] = src[(long long)(r0 + y4 + i) * lds + c0 + x];
    __syncthreads();
    #pragma unroll
    for (int i = 0; i < 4; i++)
        dst[(long long)(c0 + y4 + i) * ldd + r0 + x] = t[x][y4 + i];
}

// ---------------- LayerNorm: one block per row of E=1024 ----------------
__global__ __launch_bounds__(256) void ln_k(
    const float* __restrict__ x, const float* __restrict__ g,
    const float* __restrict__ b, float* __restrict__ y)
{
    __shared__ float sh_s[8];
    __shared__ float sh_q[8];
    long long row = blockIdx.x;
    const float* xr = x + row * Ez;
    int t = threadIdx.x;

    float4 v = reinterpret_cast<const float4*>(xr)[t];
    float s  = v.x + v.y + v.z + v.w;
    float sq = v.x * v.x + v.y * v.y + v.z * v.z + v.w * v.w;
    #pragma unroll
    for (int o = 16; o > 0; o >>= 1) {
        s  += __shfl_down_sync(0xffffffffu, s,  o);
        sq += __shfl_down_sync(0xffffffffu, sq, o);
    }
    int warp = t >> 5, lane = t & 31;
    if (lane == 0) { sh_s[warp] = s; sh_q[warp] = sq; }
    __syncthreads();
    if (warp == 0) {
        s  = (lane < 8) ? sh_s[lane] : 0.f;
        sq = (lane < 8) ? sh_q[lane] : 0.f;
        #pragma unroll
        for (int o = 4; o > 0; o >>= 1) {
            s  += __shfl_down_sync(0xffffffffu, s,  o);
            sq += __shfl_down_sync(0xffffffffu, sq, o);
        }
        if (lane == 0) { sh_s[0] = s; sh_q[0] = sq; }
    }
    __syncthreads();
    float mu  = sh_s[0] * (1.f / Ez);
    float var = sh_q[0] * (1.f / Ez) - mu * mu;
    float inv = rsqrtf(var + 1e-5f);

    float4 gg = reinterpret_cast<const float4*>(g)[t];
    float4 bb = reinterpret_cast<const float4*>(b)[t];
    float4 o;
    o.x = (v.x - mu) * inv * gg.x + bb.x;
    o.y = (v.y - mu) * inv * gg.y + bb.y;
    o.z = (v.z - mu) * inv * gg.z + bb.z;
    o.w = (v.w - mu) * inv * gg.w + bb.w;
    reinterpret_cast<float4*>(y + row * Ez)[t] = o;
}

// ---------------- driver ----------------
extern "C" void kernel_launch(void* const* d_in, const int* in_sizes, int n_in,
                              void* d_out, int out_size)
{
    (void)in_sizes; (void)n_in; (void)out_size;
    const float* x      = (const float*)d_in[0];
    const float* ln1_g  = (const float*)d_in[1];
    const float* ln1_b  = (const float*)d_in[2];
    const float* W_qkv  = (const float*)d_in[3];
    const float* W_proj = (const float*)d_in[4];
    const float* b_proj = (const float*)d_in[5];
    const float* ln2_g  = (const float*)d_in[6];
    const float* ln2_b  = (const float*)d_in[7];
    const float* W1     = (const float*)d_in[8];
    const float* b1     = (const float*)d_in[9];
    const float* W2     = (const float*)d_in[10];
    const float* b2     = (const float*)d_in[11];
    float* out = (float*)d_out;

    float *h, *qkv, *att, *x1, *ffn, *wqkvT, *wprojT, *w1T, *w2T, *vT;
    cudaGetSymbolAddress((void**)&h,      g_h);
    cudaGetSymbolAddress((void**)&qkv,    g_qkv);
    cudaGetSymbolAddress((void**)&att,    g_att);
    cudaGetSymbolAddress((void**)&x1,     g_x1);
    cudaGetSymbolAddress((void**)&ffn,    g_ffn);
    cudaGetSymbolAddress((void**)&wqkvT,  g_wqkvT);
    cudaGetSymbolAddress((void**)&wprojT, g_wprojT);
    cudaGetSymbolAddress((void**)&w1T,    g_w1T);
    cudaGetSymbolAddress((void**)&w2T,    g_w2T);
    cudaGetSymbolAddress((void**)&vT,     g_vT);

    const int FLASH_SMEM = (2 * 128 * QLD + 64 * VLD + 128 * VLD + 3 * 128) * 4;
    cudaFuncSetAttribute(flash_k, cudaFuncAttributeMaxDynamicSharedMemorySize, FLASH_SMEM);

    // 1. h = LN1(x)
    ln_k<<<BLz, 256>>>(x, ln1_g, ln1_b, h);

    // 2. one-shot weight transposes -> [N][K] K-major operands
    transpose_k<<<dim3(E3z / 32, Ez / 32, 1), 256>>>(W_qkv,  wqkvT,  E3z, Ez,  1, 0, 0, 0, 0);
    transpose_k<<<dim3(Ez  / 32, Ez / 32, 1), 256>>>(W_proj, wprojT, Ez,  Ez,  1, 0, 0, 0, 0);
    transpose_k<<<dim3(FFz / 32, Ez / 32, 1), 256>>>(W1,     w1T,    FFz, Ez,  1, 0, 0, 0, 0);
    transpose_k<<<dim3(Ez  / 32, FFz / 32, 1), 256>>>(W2,    w2T,    Ez,  FFz, 1, 0, 0, 0, 0);

    // 3. qkv = h @ W_qkv
    mma_gemm<128, EPI_NONE><<<dim3(E3z / 128, BLz / 128, 1), 256>>>(
        h, wqkvT, qkv, nullptr, nullptr,
        Ez, Ez, Ez, E3z, 1, 0, 0, 0, 0, 0, 0);

    // 4. vT[b,h] = V[b,h]^T  ([D][L] per head)
    transpose_k<<<dim3(Dz / 32, Lz / 32, Bz * Hz), 256>>>(
        qkv + 2 * Ez, vT, E3z, Lz, Hz,
        (long long)Lz * E3z, Dz,
        (long long)Hz * Dz * Lz, (long long)Dz * Lz);

    // 5. att = flash(Q, K, V)  — fused QK^T + softmax + PV
    flash_k<<<dim3(Lz / 128, Bz * Hz), 256, FLASH_SMEM>>>(qkv, vT, att);

    // 6. x1 = x + att @ W_proj + b_proj
    mma_gemm<128, EPI_BIAS_RES><<<dim3(Ez / 128, BLz / 128, 1), 256>>>(
        att, wprojT, x1, b_proj, x,
        Ez, Ez, Ez, Ez, 1, 0, 0, 0, 0, 0, 0);

    // 7. h = LN2(x1)
    ln_k<<<BLz, 256>>>(x1, ln2_g, ln2_b, h);

    // 8. ffn = gelu(h @ W1 + b1)
    mma_gemm<128, EPI_BIAS_GELU><<<dim3(FFz / 128, BLz / 128, 1), 256>>>(
        h, w1T, ffn, b1, nullptr,
        Ez, Ez, Ez, FFz, 1, 0, 0, 0, 0, 0, 0);

    // 9. out = x1 + ffn @ W2 + b2
    mma_gemm<128, EPI_BIAS_RES><<<dim3(Ez / 128, BLz / 128, 1), 256>>>(
        ffn, w2T, out, b2, x1,
        FFz, FFz, FFz, Ez, 1, 0, 0, 0, 0, 0, 0);
}